// round 1
// baseline (speedup 1.0000x reference)
#include <cuda_runtime.h>
#include <math.h>

#define N 2048

// Scratch (allocation-free rule: __device__ globals)
__device__ float g_A[N * N];   // x @ q
__device__ float g_B[N * N];   // x @ k
__device__ float g_C[N * N];   // x @ v
__device__ float g_QK[N * N];  // (x@q) @ (x@k), then softmax in place

// ---------------------------------------------------------------------------
// SGEMM: C = A @ B, all row-major [N x N], N multiple of 128.
// Tile: BM=BN=128, BK=8; 256 threads; 8x8 per-thread microtile.
// ---------------------------------------------------------------------------
__global__ __launch_bounds__(256, 2) void sgemm_kernel(
    const float* __restrict__ A, const float* __restrict__ B,
    float* __restrict__ C)
{
    __shared__ float As[8][128];   // transposed: As[k][m]
    __shared__ float Bs[8][128];   // Bs[k][n]

    const int tid  = threadIdx.x;
    const int brow = blockIdx.y * 128;
    const int bcol = blockIdx.x * 128;

    // A tile load: 128 rows x 8 k — one float4 (along k) per thread
    const int aRow = tid >> 1;           // 0..127
    const int aK   = (tid & 1) * 4;      // 0 or 4
    // B tile load: 8 k x 128 cols — one float4 (along n) per thread
    const int bRow = tid >> 5;           // 0..7
    const int bCol = (tid & 31) * 4;     // 0..124

    // compute mapping: 16x16 thread grid of 8x8 microtiles
    const int rm = (tid >> 4) * 8;       // row offset in tile
    const int cn = (tid & 15) * 8;       // col offset in tile

    float acc[8][8];
#pragma unroll
    for (int i = 0; i < 8; i++)
#pragma unroll
        for (int j = 0; j < 8; j++) acc[i][j] = 0.0f;

    const float* Aptr = A + (size_t)(brow + aRow) * N + aK;
    const float* Bptr = B + (size_t)bRow * N + bcol + bCol;

    for (int k0 = 0; k0 < N; k0 += 8) {
        // load A tile (transposed into As)
        float4 a4 = *(const float4*)(Aptr + k0);
        As[aK + 0][aRow] = a4.x;
        As[aK + 1][aRow] = a4.y;
        As[aK + 2][aRow] = a4.z;
        As[aK + 3][aRow] = a4.w;
        // load B tile
        float4 b4 = *(const float4*)(Bptr + (size_t)k0 * N);
        *(float4*)&Bs[bRow][bCol] = b4;
        __syncthreads();

#pragma unroll
        for (int k = 0; k < 8; k++) {
            float ra[8], rb[8];
            *(float4*)&ra[0] = *(const float4*)&As[k][rm];
            *(float4*)&ra[4] = *(const float4*)&As[k][rm + 4];
            *(float4*)&rb[0] = *(const float4*)&Bs[k][cn];
            *(float4*)&rb[4] = *(const float4*)&Bs[k][cn + 4];
#pragma unroll
            for (int i = 0; i < 8; i++)
#pragma unroll
                for (int j = 0; j < 8; j++)
                    acc[i][j] = fmaf(ra[i], rb[j], acc[i][j]);
        }
        __syncthreads();
    }

    // store 8x8 microtile
#pragma unroll
    for (int i = 0; i < 8; i++) {
        float* crow = C + (size_t)(brow + rm + i) * N + bcol + cn;
        *(float4*)(crow + 0) = *(float4*)&acc[i][0];
        *(float4*)(crow + 4) = *(float4*)&acc[i][4];
    }
}

// ---------------------------------------------------------------------------
// Row softmax in place: one block per row, 256 threads, 8 elems/thread.
// ---------------------------------------------------------------------------
__global__ __launch_bounds__(256) void softmax_rows_kernel(float* __restrict__ M)
{
    __shared__ float red[256];
    const int row = blockIdx.x;
    const int tid = threadIdx.x;
    float* r = M + (size_t)row * N;

    float vals[8];
    float lmax = -INFINITY;
#pragma unroll
    for (int i = 0; i < 8; i++) {
        vals[i] = r[tid + i * 256];
        lmax = fmaxf(lmax, vals[i]);
    }
    red[tid] = lmax;
    __syncthreads();
#pragma unroll
    for (int s = 128; s > 0; s >>= 1) {
        if (tid < s) red[tid] = fmaxf(red[tid], red[tid + s]);
        __syncthreads();
    }
    const float m = red[0];
    __syncthreads();

    float lsum = 0.0f;
#pragma unroll
    for (int i = 0; i < 8; i++) {
        vals[i] = expf(vals[i] - m);
        lsum += vals[i];
    }
    red[tid] = lsum;
    __syncthreads();
#pragma unroll
    for (int s = 128; s > 0; s >>= 1) {
        if (tid < s) red[tid] += red[tid + s];
        __syncthreads();
    }
    const float inv = 1.0f / red[0];
#pragma unroll
    for (int i = 0; i < 8; i++) {
        r[tid + i * 256] = vals[i] * inv;
    }
}

// ---------------------------------------------------------------------------
// kernel_launch
// inputs (metadata order): x, q, k, v  — all float32 [N*N]
// out: float32 [N*N]
// ---------------------------------------------------------------------------
extern "C" void kernel_launch(void* const* d_in, const int* in_sizes, int n_in,
                              void* d_out, int out_size)
{
    const float* x = (const float*)d_in[0];
    const float* q = (const float*)d_in[1];
    const float* k = (const float*)d_in[2];
    const float* v = (const float*)d_in[3];
    float* out = (float*)d_out;

    float *pA, *pB, *pC, *pQK;
    cudaGetSymbolAddress((void**)&pA,  g_A);
    cudaGetSymbolAddress((void**)&pB,  g_B);
    cudaGetSymbolAddress((void**)&pC,  g_C);
    cudaGetSymbolAddress((void**)&pQK, g_QK);

    dim3 grid(N / 128, N / 128);
    dim3 block(256);

    sgemm_kernel<<<grid, block>>>(x, q, pA);    // A = x @ q
    sgemm_kernel<<<grid, block>>>(x, k, pB);    // B = x @ k
    sgemm_kernel<<<grid, block>>>(x, v, pC);    // C = x @ v
    sgemm_kernel<<<grid, block>>>(pA, pB, pQK); // QK = A @ B
    softmax_rows_kernel<<<N, block>>>(pQK);     // softmax rows in place
    sgemm_kernel<<<grid, block>>>(pQK, pC, out);// out = attn @ C
}

// round 3
// speedup vs baseline: 1.5893x; 1.5893x over previous
#include <cuda_runtime.h>
#include <cuda_bf16.h>
#include <math.h>
#include <stdint.h>

#define N 2048
#define NN (N * N)

// ---------------------------------------------------------------------------
// Scratch (__device__ globals; allocation-free rule)
// ---------------------------------------------------------------------------
__device__ float g_A1[NN];   // x @ q (fp32)
__device__ float g_B1[NN];   // x @ k (fp32)
__device__ float g_C1[NN];   // x @ v (fp32)
__device__ float g_QK[NN];   // logits -> softmax in place

// 3-plane bf16 splits. A-form: [M,K] row-major. B-form: [N,K] row-major (=B^T).
__device__ __nv_bfloat16 g_xS[3][NN];    // A-form
__device__ __nv_bfloat16 g_qS[3][NN];    // B-form
__device__ __nv_bfloat16 g_kS[3][NN];    // B-form
__device__ __nv_bfloat16 g_vS[3][NN];    // B-form
__device__ __nv_bfloat16 g_A1S[3][NN];   // A-form
__device__ __nv_bfloat16 g_B1S[3][NN];   // B-form
__device__ __nv_bfloat16 g_C1S[3][NN];   // B-form
__device__ __nv_bfloat16 g_atS[3][NN];   // A-form

// ---------------------------------------------------------------------------
// PTX helpers (all legal on plain compute_103: sm_80-era instructions)
// ---------------------------------------------------------------------------
__device__ __forceinline__ uint32_t smem_to_u32(const void* p) {
    uint32_t a;
    asm("{ .reg .u64 t; cvta.to.shared.u64 t, %1; cvt.u32.u64 %0, t; }"
        : "=r"(a) : "l"(p));
    return a;
}
__device__ __forceinline__ void cp_async16(uint32_t saddr, const void* gaddr) {
    asm volatile("cp.async.cg.shared.global [%0], [%1], 16;"
                 :: "r"(saddr), "l"(gaddr) : "memory");
}
__device__ __forceinline__ void cp_commit() {
    asm volatile("cp.async.commit_group;" ::: "memory");
}
__device__ __forceinline__ void ldsm4(uint32_t* r, uint32_t addr) {
    asm volatile("ldmatrix.sync.aligned.m8n8.x4.shared.b16 {%0,%1,%2,%3}, [%4];"
                 : "=r"(r[0]), "=r"(r[1]), "=r"(r[2]), "=r"(r[3]) : "r"(addr));
}
__device__ __forceinline__ void mma16816(float* c, const uint32_t* a,
                                         uint32_t b0, uint32_t b1) {
    asm volatile(
        "mma.sync.aligned.m16n8k16.row.col.f32.bf16.bf16.f32 "
        "{%0,%1,%2,%3}, {%4,%5,%6,%7}, {%8,%9}, {%0,%1,%2,%3};"
        : "+f"(c[0]), "+f"(c[1]), "+f"(c[2]), "+f"(c[3])
        : "r"(a[0]), "r"(a[1]), "r"(a[2]), "r"(a[3]), "r"(b0), "r"(b1));
}

// ---------------------------------------------------------------------------
// GEMM: C[M,N] fp32 = sum_t A[pa[t]] @ B[pb[t]]^T   (bf16 split planes)
// Tile 128x128, BK=32, 256 threads (2x4 warps, 64x32 warp tile), 2-stage cp.async.
// smem tile: 128 rows x 80B (32 bf16 + 8 pad) = 10240B per plane-tile.
// ---------------------------------------------------------------------------
template <int NTERMS, int NPA, int NPB>
__global__ __launch_bounds__(256, 1) void gemm_terms_kernel(
    const __nv_bfloat16* __restrict__ A,   // [NPA][M][K] planes
    const __nv_bfloat16* __restrict__ B,   // [NPB][N][K] planes
    float* __restrict__ C)
{
    extern __shared__ char smem[];
    constexpr int TILEB = 10240;
    constexpr int STAGE = (NPA + NPB) * TILEB;

    const uint32_t sbase = smem_to_u32(smem);
    const int tid  = threadIdx.x;
    const int lane = tid & 31;
    const int wid  = tid >> 5;
    const int wm   = wid >> 2;            // 0..1
    const int wn   = wid & 3;             // 0..3
    const int brow = blockIdx.y * 128;
    const int bcol = blockIdx.x * 128;

    float acc[4][4][4];
#pragma unroll
    for (int i = 0; i < 4; i++)
#pragma unroll
        for (int j = 0; j < 4; j++)
#pragma unroll
            for (int q = 0; q < 4; q++) acc[i][j][q] = 0.0f;

    // ---- stage loader: 512 16B-chunks per plane-tile; 2 chunks/thread/plane
    auto load_stage = [&](int s, int k0) {
        const uint32_t st = sbase + s * STAGE;
#pragma unroll
        for (int p = 0; p < NPA; p++) {
            const __nv_bfloat16* src = A + (size_t)p * NN;
#pragma unroll
            for (int rep = 0; rep < 2; rep++) {
                const int idx = rep * 256 + tid;
                const int row = idx >> 2;
                const int ch  = idx & 3;
                cp_async16(st + p * TILEB + row * 80 + ch * 16,
                           src + (size_t)(brow + row) * N + k0 + ch * 8);
            }
        }
#pragma unroll
        for (int p = 0; p < NPB; p++) {
            const __nv_bfloat16* src = B + (size_t)p * NN;
#pragma unroll
            for (int rep = 0; rep < 2; rep++) {
                const int idx = rep * 256 + tid;
                const int row = idx >> 2;
                const int ch  = idx & 3;
                cp_async16(st + (NPA + p) * TILEB + row * 80 + ch * 16,
                           src + (size_t)(bcol + row) * N + k0 + ch * 8);
            }
        }
        cp_commit();
    };

    // term plane index tables
    constexpr int pa6[6] = {0, 0, 1, 1, 0, 2};
    constexpr int pb6[6] = {0, 1, 0, 1, 2, 0};
    constexpr int pa3[3] = {0, 0, 1};
    constexpr int pb3[3] = {0, 1, 0};

    auto compute_stage = [&](int s) {
        const uint32_t st = sbase + s * STAGE;
#pragma unroll
        for (int t = 0; t < NTERMS; t++) {
            const int pa = (NTERMS == 6) ? pa6[t] : pa3[t];
            const int pb = (NTERMS == 6) ? pb6[t] : pb3[t];
            const uint32_t sA = st + pa * TILEB;
            const uint32_t sB = st + (NPA + pb) * TILEB;
#pragma unroll
            for (int ks = 0; ks < 2; ks++) {
                uint32_t a[4][4];
                const uint32_t arow  = wm * 64 + (lane & 15);
                const uint32_t acol2 = (ks * 16 + ((lane >> 4) << 3)) * 2;
#pragma unroll
                for (int mf = 0; mf < 4; mf++)
                    ldsm4(a[mf], sA + (arow + mf * 16) * 80 + acol2);

                uint32_t b[2][4];
                const uint32_t brw   = wn * 32 + (lane & 7) + ((lane >> 4) << 3);
                const uint32_t bcol2 = (ks * 16 + ((lane >> 3) & 1) * 8) * 2;
#pragma unroll
                for (int nh = 0; nh < 2; nh++)
                    ldsm4(b[nh], sB + (brw + nh * 16) * 80 + bcol2);

#pragma unroll
                for (int mf = 0; mf < 4; mf++)
#pragma unroll
                    for (int nf = 0; nf < 4; nf++)
                        mma16816(acc[mf][nf], a[mf],
                                 b[nf >> 1][(nf & 1) * 2],
                                 b[nf >> 1][(nf & 1) * 2 + 1]);
            }
        }
    };

    // ---- pipelined mainloop (K = 2048, BK = 32 -> 64 iters, 2 stages)
    load_stage(0, 0);
    for (int it = 0; it < 64; it++) {
        if (it + 1 < 64) {
            load_stage((it + 1) & 1, (it + 1) * 32);
            asm volatile("cp.async.wait_group 1;" ::: "memory");
        } else {
            asm volatile("cp.async.wait_group 0;" ::: "memory");
        }
        __syncthreads();
        compute_stage(it & 1);
        __syncthreads();
    }

    // ---- epilogue
    const int row0 = brow + wm * 64 + (lane >> 2);
    const int col0 = bcol + wn * 32 + (lane & 3) * 2;
#pragma unroll
    for (int mf = 0; mf < 4; mf++) {
#pragma unroll
        for (int nf = 0; nf < 4; nf++) {
            float2 lo = make_float2(acc[mf][nf][0], acc[mf][nf][1]);
            float2 hi = make_float2(acc[mf][nf][2], acc[mf][nf][3]);
            *(float2*)&C[(size_t)(row0 + mf * 16) * N + col0 + nf * 8]     = lo;
            *(float2*)&C[(size_t)(row0 + mf * 16 + 8) * N + col0 + nf * 8] = hi;
        }
    }
}

// ---------------------------------------------------------------------------
// Split fp32 -> 3x bf16 planes, same layout (A-form)
// ---------------------------------------------------------------------------
__global__ __launch_bounds__(256) void split_kernel(
    const float* __restrict__ in, __nv_bfloat16* __restrict__ out)
{
    const int i = blockIdx.x * blockDim.x + threadIdx.x;
    const float2 a = *(const float2*)(in + 2 * (size_t)i);

    __nv_bfloat16 h1x = __float2bfloat16_rn(a.x);
    __nv_bfloat16 h1y = __float2bfloat16_rn(a.y);
    float rx = a.x - __bfloat162float(h1x);
    float ry = a.y - __bfloat162float(h1y);
    __nv_bfloat16 h2x = __float2bfloat16_rn(rx);
    __nv_bfloat16 h2y = __float2bfloat16_rn(ry);
    float sx = rx - __bfloat162float(h2x);
    float sy = ry - __bfloat162float(h2y);
    __nv_bfloat16 h3x = __float2bfloat16_rn(sx);
    __nv_bfloat16 h3y = __float2bfloat16_rn(sy);

    *(__nv_bfloat162*)(out + 2 * (size_t)i)                  = __nv_bfloat162(h1x, h1y);
    *(__nv_bfloat162*)(out + (size_t)NN + 2 * (size_t)i)     = __nv_bfloat162(h2x, h2y);
    *(__nv_bfloat162*)(out + 2 * (size_t)NN + 2 * (size_t)i) = __nv_bfloat162(h3x, h3y);
}

// ---------------------------------------------------------------------------
// Split + transpose: fp32 [K,N] -> 3x bf16 [N,K] planes (B-form)
// ---------------------------------------------------------------------------
__global__ __launch_bounds__(256) void split_transpose_kernel(
    const float* __restrict__ in, __nv_bfloat16* __restrict__ out)
{
    __shared__ float t[32][33];
    const int tx = threadIdx.x;          // 0..31
    const int ty = threadIdx.y;          // 0..7
    const int k0 = blockIdx.y * 32;
    const int n0 = blockIdx.x * 32;

#pragma unroll
    for (int r = ty; r < 32; r += 8)
        t[r][tx] = in[(size_t)(k0 + r) * N + n0 + tx];
    __syncthreads();

#pragma unroll
    for (int r = ty; r < 32; r += 8) {
        float a = t[tx][r];              // = in[k0+tx][n0+r]
        __nv_bfloat16 h1 = __float2bfloat16_rn(a);
        float rr = a - __bfloat162float(h1);
        __nv_bfloat16 h2 = __float2bfloat16_rn(rr);
        float ss = rr - __bfloat162float(h2);
        __nv_bfloat16 h3 = __float2bfloat16_rn(ss);
        const size_t o = (size_t)(n0 + r) * N + k0 + tx;
        out[o]                  = h1;
        out[(size_t)NN + o]     = h2;
        out[2 * (size_t)NN + o] = h3;
    }
}

// ---------------------------------------------------------------------------
// Row softmax in place
// ---------------------------------------------------------------------------
__global__ __launch_bounds__(256) void softmax_rows_kernel(float* __restrict__ M)
{
    __shared__ float red[256];
    const int row = blockIdx.x;
    const int tid = threadIdx.x;
    float* r = M + (size_t)row * N;

    float vals[8];
    float lmax = -INFINITY;
#pragma unroll
    for (int i = 0; i < 8; i++) {
        vals[i] = r[tid + i * 256];
        lmax = fmaxf(lmax, vals[i]);
    }
    red[tid] = lmax;
    __syncthreads();
#pragma unroll
    for (int s = 128; s > 0; s >>= 1) {
        if (tid < s) red[tid] = fmaxf(red[tid], red[tid + s]);
        __syncthreads();
    }
    const float m = red[0];
    __syncthreads();

    float lsum = 0.0f;
#pragma unroll
    for (int i = 0; i < 8; i++) {
        vals[i] = expf(vals[i] - m);
        lsum += vals[i];
    }
    red[tid] = lsum;
    __syncthreads();
#pragma unroll
    for (int s = 128; s > 0; s >>= 1) {
        if (tid < s) red[tid] += red[tid + s];
        __syncthreads();
    }
    const float inv = 1.0f / red[0];
#pragma unroll
    for (int i = 0; i < 8; i++) {
        r[tid + i * 256] = vals[i] * inv;
    }
}

// ---------------------------------------------------------------------------
// kernel_launch  —  inputs (metadata order): x, q, k, v  (float32 [N*N])
// ---------------------------------------------------------------------------
extern "C" void kernel_launch(void* const* d_in, const int* in_sizes, int n_in,
                              void* d_out, int out_size)
{
    const float* x = (const float*)d_in[0];
    const float* q = (const float*)d_in[1];
    const float* k = (const float*)d_in[2];
    const float* v = (const float*)d_in[3];
    float* out = (float*)d_out;

    float *pA1, *pB1, *pC1, *pQK;
    cudaGetSymbolAddress((void**)&pA1, g_A1);
    cudaGetSymbolAddress((void**)&pB1, g_B1);
    cudaGetSymbolAddress((void**)&pC1, g_C1);
    cudaGetSymbolAddress((void**)&pQK, g_QK);

    __nv_bfloat16 *pxS, *pqS, *pkS, *pvS, *pA1S, *pB1S, *pC1S, *patS;
    cudaGetSymbolAddress((void**)&pxS,  g_xS);
    cudaGetSymbolAddress((void**)&pqS,  g_qS);
    cudaGetSymbolAddress((void**)&pkS,  g_kS);
    cudaGetSymbolAddress((void**)&pvS,  g_vS);
    cudaGetSymbolAddress((void**)&pA1S, g_A1S);
    cudaGetSymbolAddress((void**)&pB1S, g_B1S);
    cudaGetSymbolAddress((void**)&pC1S, g_C1S);
    cudaGetSymbolAddress((void**)&patS, g_atS);

    constexpr int SMEM6 = 2 * 6 * 10240;   // 122880
    constexpr int SMEM3 = 2 * 4 * 10240;   // 81920
    cudaFuncSetAttribute(gemm_terms_kernel<6, 3, 3>,
                         cudaFuncAttributeMaxDynamicSharedMemorySize, SMEM6);
    cudaFuncSetAttribute(gemm_terms_kernel<3, 2, 2>,
                         cudaFuncAttributeMaxDynamicSharedMemorySize, SMEM3);

    const dim3 gGemm(N / 128, N / 128);
    const dim3 gSplit(NN / 512);
    const dim3 gTr(N / 32, N / 32);
    const dim3 bTr(32, 8);

    // split inputs
    split_kernel<<<gSplit, 256>>>(x, pxS);
    split_transpose_kernel<<<gTr, bTr>>>(q, pqS);
    split_transpose_kernel<<<gTr, bTr>>>(k, pkS);
    split_transpose_kernel<<<gTr, bTr>>>(v, pvS);

    // first layer
    gemm_terms_kernel<6, 3, 3><<<gGemm, 256, SMEM6>>>(pxS, pqS, pA1);  // x@q
    gemm_terms_kernel<6, 3, 3><<<gGemm, 256, SMEM6>>>(pxS, pkS, pB1);  // x@k
    gemm_terms_kernel<3, 2, 2><<<gGemm, 256, SMEM3>>>(pxS, pvS, pC1);  // x@v

    // re-split intermediates
    split_kernel<<<gSplit, 256>>>(pA1, pA1S);
    split_transpose_kernel<<<gTr, bTr>>>(pB1, pB1S);
    split_transpose_kernel<<<gTr, bTr>>>(pC1, pC1S);

    // logits + softmax
    gemm_terms_kernel<6, 3, 3><<<gGemm, 256, SMEM6>>>(pA1S, pB1S, pQK);
    softmax_rows_kernel<<<N, 256>>>(pQK);
    split_kernel<<<gSplit, 256>>>(pQK, patS);

    // output
    gemm_terms_kernel<3, 2, 2><<<gGemm, 256, SMEM3>>>(patS, pC1S, out);
}

// round 4
// speedup vs baseline: 2.7625x; 1.7382x over previous
#include <cuda_runtime.h>
#include <cuda_fp16.h>
#include <math.h>
#include <stdint.h>

#define N 2048
#define NN (N * N)

// ---------------------------------------------------------------------------
// Scratch (__device__ globals; allocation-free rule)
// Each split tensor = 2 fp16 planes [hi, lo], layout [2][NN].
// A-form: [M,K] row-major of the matrix. B-form: [N,K] row-major (= M^T).
// ---------------------------------------------------------------------------
__device__ float  g_QK[NN];      // logits (fp32), softmax input
__device__ __half g_xS[2][NN];   // x      A-form
__device__ __half g_qS[2][NN];   // q^T    B-form
__device__ __half g_kS[2][NN];   // k^T    B-form
__device__ __half g_vS[2][NN];   // v^T    B-form
__device__ __half g_A1S[2][NN];  // (x@q)      A-form
__device__ __half g_B1S[2][NN];  // (x@k)^T    B-form
__device__ __half g_C1S[2][NN];  // (x@v)^T    B-form
__device__ __half g_atS[2][NN];  // softmax(QK) A-form

// ---------------------------------------------------------------------------
// PTX helpers (sm_80-era, legal on compute_103)
// ---------------------------------------------------------------------------
__device__ __forceinline__ uint32_t smem_to_u32(const void* p) {
    uint32_t a;
    asm("{ .reg .u64 t; cvta.to.shared.u64 t, %1; cvt.u32.u64 %0, t; }"
        : "=r"(a) : "l"(p));
    return a;
}
__device__ __forceinline__ void cp_async16(uint32_t saddr, const void* gaddr) {
    asm volatile("cp.async.cg.shared.global [%0], [%1], 16;"
                 :: "r"(saddr), "l"(gaddr) : "memory");
}
__device__ __forceinline__ void cp_commit() {
    asm volatile("cp.async.commit_group;" ::: "memory");
}
__device__ __forceinline__ void ldsm4(uint32_t* r, uint32_t addr) {
    asm volatile("ldmatrix.sync.aligned.m8n8.x4.shared.b16 {%0,%1,%2,%3}, [%4];"
                 : "=r"(r[0]), "=r"(r[1]), "=r"(r[2]), "=r"(r[3]) : "r"(addr));
}
__device__ __forceinline__ void mma16816(float* c, const uint32_t* a,
                                         uint32_t b0, uint32_t b1) {
    asm volatile(
        "mma.sync.aligned.m16n8k16.row.col.f32.f16.f16.f32 "
        "{%0,%1,%2,%3}, {%4,%5,%6,%7}, {%8,%9}, {%0,%1,%2,%3};"
        : "+f"(c[0]), "+f"(c[1]), "+f"(c[2]), "+f"(c[3])
        : "r"(a[0]), "r"(a[1]), "r"(a[2]), "r"(a[3]), "r"(b0), "r"(b1));
}

// ---------------------------------------------------------------------------
// GEMM: C[M,N] = Ah@Bh^T + Ah@Bl^T + Al@Bh^T   (fp16 planes, fp32 accum)
//   A: [2][M][K] planes (A-form), B: [2][N][K] planes (B-form)
// Tile 128x128, BK=32, 256 thr (2x4 warps, 64x32 warp tile), 3-stage cp.async.
// If SPLIT: epilogue writes fp16 hi/lo planes of C; else fp32 C.
// ---------------------------------------------------------------------------
#define TILEB 10240                 // 128 rows * 80B (64B data + 16B pad)
#define STAGE (4 * TILEB)           // Ah, Al, Bh, Bl
#define SMEM_GEMM (3 * STAGE)       // 3 stages = 122880 B

template <bool SPLIT>
__global__ __launch_bounds__(256, 1) void gemm3_kernel(
    const __half* __restrict__ A,    // [2][NN]
    const __half* __restrict__ B,    // [2][NN]
    float* __restrict__ Cf,          // used if !SPLIT
    __half* __restrict__ Cp)         // [2][NN], used if SPLIT
{
    extern __shared__ char smem[];
    const uint32_t sbase = smem_to_u32(smem);
    const int tid  = threadIdx.x;
    const int lane = tid & 31;
    const int wid  = tid >> 5;
    const int wm   = wid >> 2;            // 0..1
    const int wn   = wid & 3;             // 0..3
    const int brow = blockIdx.y * 128;
    const int bcol = blockIdx.x * 128;

    float acc[4][4][4];
#pragma unroll
    for (int i = 0; i < 4; i++)
#pragma unroll
        for (int j = 0; j < 4; j++)
#pragma unroll
            for (int q = 0; q < 4; q++) acc[i][j][q] = 0.0f;

    // per-thread load coords: 512 chunks of 16B per plane-tile -> 2/thread
    const int lrow0 = tid >> 2;           // 0..63
    const int lch   = tid & 3;            // 0..3

    auto load_stage = [&](int s, int k0) {
        const uint32_t st = sbase + s * STAGE;
#pragma unroll
        for (int p = 0; p < 2; p++) {
            const __half* src = A + (size_t)p * NN;
#pragma unroll
            for (int rep = 0; rep < 2; rep++) {
                const int row = lrow0 + rep * 64;
                cp_async16(st + p * TILEB + row * 80 + lch * 16,
                           src + (size_t)(brow + row) * N + k0 + lch * 8);
            }
        }
#pragma unroll
        for (int p = 0; p < 2; p++) {
            const __half* src = B + (size_t)p * NN;
#pragma unroll
            for (int rep = 0; rep < 2; rep++) {
                const int row = lrow0 + rep * 64;
                cp_async16(st + (2 + p) * TILEB + row * 80 + lch * 16,
                           src + (size_t)(bcol + row) * N + k0 + lch * 8);
            }
        }
        cp_commit();
    };

    auto compute_stage = [&](int s) {
        const uint32_t st = sbase + s * STAGE;
#pragma unroll
        for (int ks = 0; ks < 2; ks++) {
            // load fragments for both A planes and both B planes
            uint32_t a[2][4][4];
            const uint32_t arow  = wm * 64 + (lane & 15);
            const uint32_t acol2 = (ks * 16 + ((lane >> 4) << 3)) * 2;
#pragma unroll
            for (int p = 0; p < 2; p++)
#pragma unroll
                for (int mf = 0; mf < 4; mf++)
                    ldsm4(a[p][mf],
                          st + p * TILEB + (arow + mf * 16) * 80 + acol2);

            uint32_t b[2][2][4];
            const uint32_t brw   = wn * 32 + (lane & 7) + ((lane >> 4) << 3);
            const uint32_t bcol2 = (ks * 16 + ((lane >> 3) & 1) * 8) * 2;
#pragma unroll
            for (int p = 0; p < 2; p++)
#pragma unroll
                for (int nh = 0; nh < 2; nh++)
                    ldsm4(b[p][nh],
                          st + (2 + p) * TILEB + (brw + nh * 16) * 80 + bcol2);

            // 3 terms: (Ah,Bh), (Ah,Bl), (Al,Bh)
#pragma unroll
            for (int t = 0; t < 3; t++) {
                const int pa = (t == 2) ? 1 : 0;
                const int pb = (t == 1) ? 1 : 0;
#pragma unroll
                for (int mf = 0; mf < 4; mf++)
#pragma unroll
                    for (int nf = 0; nf < 4; nf++)
                        mma16816(acc[mf][nf], a[pa][mf],
                                 b[pb][nf >> 1][(nf & 1) * 2],
                                 b[pb][nf >> 1][(nf & 1) * 2 + 1]);
            }
        }
    };

    // ---- 3-stage pipeline, K = 2048 -> 64 iters
    load_stage(0, 0);
    load_stage(1, 32);
    for (int it = 0; it < 64; it++) {
        if (it < 63) {
            asm volatile("cp.async.wait_group 1;" ::: "memory");
        } else {
            asm volatile("cp.async.wait_group 0;" ::: "memory");
        }
        __syncthreads();
        compute_stage(it % 3);
        if (it + 2 < 64) load_stage((it + 2) % 3, (it + 2) * 32);
    }

    // ---- epilogue
    const int row0 = brow + wm * 64 + (lane >> 2);
    const int col0 = bcol + wn * 32 + (lane & 3) * 2;
#pragma unroll
    for (int mf = 0; mf < 4; mf++) {
#pragma unroll
        for (int nf = 0; nf < 4; nf++) {
#pragma unroll
            for (int half_id = 0; half_id < 2; half_id++) {
                const size_t off = (size_t)(row0 + mf * 16 + half_id * 8) * N
                                   + col0 + nf * 8;
                float c0 = acc[mf][nf][half_id * 2];
                float c1 = acc[mf][nf][half_id * 2 + 1];
                if (SPLIT) {
                    __half h0 = __float2half_rn(c0);
                    __half h1 = __float2half_rn(c1);
                    __half l0 = __float2half_rn(c0 - __half2float(h0));
                    __half l1 = __float2half_rn(c1 - __half2float(h1));
                    *(__half2*)&Cp[off]                = __halves2half2(h0, h1);
                    *(__half2*)&Cp[(size_t)NN + off]   = __halves2half2(l0, l1);
                } else {
                    *(float2*)&Cf[off] = make_float2(c0, c1);
                }
            }
        }
    }
}

// ---------------------------------------------------------------------------
// Split fp32 -> 2 fp16 planes, same layout (A-form), 2 elems/thread
// ---------------------------------------------------------------------------
__global__ __launch_bounds__(256) void split_kernel(
    const float* __restrict__ in, __half* __restrict__ out)
{
    const size_t i = (size_t)blockIdx.x * blockDim.x + threadIdx.x;
    const float2 a = *(const float2*)(in + 2 * i);
    __half hx = __float2half_rn(a.x);
    __half hy = __float2half_rn(a.y);
    __half lx = __float2half_rn(a.x - __half2float(hx));
    __half ly = __float2half_rn(a.y - __half2float(hy));
    *(__half2*)(out + 2 * i)              = __halves2half2(hx, hy);
    *(__half2*)(out + (size_t)NN + 2 * i) = __halves2half2(lx, ly);
}

// ---------------------------------------------------------------------------
// Split + transpose: fp32 [K,N] -> 2 fp16 planes [N,K] (B-form)
// ---------------------------------------------------------------------------
__global__ __launch_bounds__(256) void split_transpose_kernel(
    const float* __restrict__ in, __half* __restrict__ out)
{
    __shared__ float t[32][33];
    const int tx = threadIdx.x;
    const int ty = threadIdx.y;
    const int k0 = blockIdx.y * 32;
    const int n0 = blockIdx.x * 32;

#pragma unroll
    for (int r = ty; r < 32; r += 8)
        t[r][tx] = in[(size_t)(k0 + r) * N + n0 + tx];
    __syncthreads();

#pragma unroll
    for (int r = ty; r < 32; r += 8) {
        float a = t[tx][r];
        __half h = __float2half_rn(a);
        __half l = __float2half_rn(a - __half2float(h));
        const size_t o = (size_t)(n0 + r) * N + k0 + tx;
        out[o]              = h;
        out[(size_t)NN + o] = l;
    }
}

// ---------------------------------------------------------------------------
// Row softmax (fp32 in) fused with fp16 split-out (A-form planes)
// ---------------------------------------------------------------------------
__global__ __launch_bounds__(256) void softmax_split_kernel(
    const float* __restrict__ M, __half* __restrict__ out)
{
    __shared__ float red[256];
    const int row = blockIdx.x;
    const int tid = threadIdx.x;
    const float* r = M + (size_t)row * N;

    float vals[8];
    float lmax = -INFINITY;
#pragma unroll
    for (int i = 0; i < 8; i++) {
        vals[i] = r[tid + i * 256];
        lmax = fmaxf(lmax, vals[i]);
    }
    red[tid] = lmax;
    __syncthreads();
#pragma unroll
    for (int s = 128; s > 0; s >>= 1) {
        if (tid < s) red[tid] = fmaxf(red[tid], red[tid + s]);
        __syncthreads();
    }
    const float m = red[0];
    __syncthreads();

    float lsum = 0.0f;
#pragma unroll
    for (int i = 0; i < 8; i++) {
        vals[i] = expf(vals[i] - m);
        lsum += vals[i];
    }
    red[tid] = lsum;
    __syncthreads();
#pragma unroll
    for (int s = 128; s > 0; s >>= 1) {
        if (tid < s) red[tid] += red[tid + s];
        __syncthreads();
    }
    const float inv = 1.0f / red[0];
#pragma unroll
    for (int i = 0; i < 8; i++) {
        float a = vals[i] * inv;
        __half h = __float2half_rn(a);
        __half l = __float2half_rn(a - __half2float(h));
        const size_t o = (size_t)row * N + tid + i * 256;
        out[o]              = h;
        out[(size_t)NN + o] = l;
    }
}

// ---------------------------------------------------------------------------
// kernel_launch  —  inputs (metadata order): x, q, k, v  (float32 [N*N])
// ---------------------------------------------------------------------------
extern "C" void kernel_launch(void* const* d_in, const int* in_sizes, int n_in,
                              void* d_out, int out_size)
{
    const float* x = (const float*)d_in[0];
    const float* q = (const float*)d_in[1];
    const float* k = (const float*)d_in[2];
    const float* v = (const float*)d_in[3];
    float* out = (float*)d_out;

    float* pQK;
    cudaGetSymbolAddress((void**)&pQK, g_QK);
    __half *pxS, *pqS, *pkS, *pvS, *pA1S, *pB1S, *pC1S, *patS;
    cudaGetSymbolAddress((void**)&pxS,  g_xS);
    cudaGetSymbolAddress((void**)&pqS,  g_qS);
    cudaGetSymbolAddress((void**)&pkS,  g_kS);
    cudaGetSymbolAddress((void**)&pvS,  g_vS);
    cudaGetSymbolAddress((void**)&pA1S, g_A1S);
    cudaGetSymbolAddress((void**)&pB1S, g_B1S);
    cudaGetSymbolAddress((void**)&pC1S, g_C1S);
    cudaGetSymbolAddress((void**)&patS, g_atS);

    cudaFuncSetAttribute(gemm3_kernel<true>,
                         cudaFuncAttributeMaxDynamicSharedMemorySize, SMEM_GEMM);
    cudaFuncSetAttribute(gemm3_kernel<false>,
                         cudaFuncAttributeMaxDynamicSharedMemorySize, SMEM_GEMM);

    const dim3 gGemm(N / 128, N / 128);
    const dim3 gSplit(NN / 512);
    const dim3 gTr(N / 32, N / 32);
    const dim3 bTr(32, 8);

    // input splits
    split_kernel<<<gSplit, 256>>>(x, pxS);                 // x   -> A-form
    split_transpose_kernel<<<gTr, bTr>>>(q, pqS);          // q^T -> B-form
    split_transpose_kernel<<<gTr, bTr>>>(k, pkS);          // k^T -> B-form
    split_transpose_kernel<<<gTr, bTr>>>(v, pvS);          // v^T -> B-form

    // layer 1 (split fused into epilogue; transposed products avoid transpose passes)
    gemm3_kernel<true><<<gGemm, 256, SMEM_GEMM>>>(pxS, pqS, nullptr, pA1S); // x@q   (A-form)
    gemm3_kernel<true><<<gGemm, 256, SMEM_GEMM>>>(pkS, pxS, nullptr, pB1S); // (x@k)^T = k^T@x^T (B-form)
    gemm3_kernel<true><<<gGemm, 256, SMEM_GEMM>>>(pvS, pxS, nullptr, pC1S); // (x@v)^T (B-form)

    // logits + softmax
    gemm3_kernel<false><<<gGemm, 256, SMEM_GEMM>>>(pA1S, pB1S, pQK, nullptr);
    softmax_split_kernel<<<N, 256>>>(pQK, patS);

    // output
    gemm3_kernel<false><<<gGemm, 256, SMEM_GEMM>>>(patS, pC1S, out, nullptr);
}